// round 10
// baseline (speedup 1.0000x reference)
#include <cuda_runtime.h>

#define NRK 4
#define DW  64
#define KD  256            // NR*D plane stride
#define THREADS 512
#define NB  512            // value buckets (width 1/64 over [-4,4]) == THREADS
#define YS  4              // y slots per thread (Nt <= 2048)
#define XS  4              // x slots per thread (Ns <= 2048)
#define ALM_BLOCKS 8
#define NMAX 2048          // padded column stride
#define TOTAL_BLOCKS (KD + ALM_BLOCKS)

// Static scratch (no allocation). Zero-init at load; pads never written -> 0.
__device__ float  g_sT[KD * NMAX];           // s transposed+padded: [KD][NMAX]
__device__ float  g_tT[KD * NMAX];           // t transposed+padded: [KD][NMAX]
__device__ double g_colp[KD];                // per-column partials
__device__ double g_almp[ALM_BLOCKS * NRK];  // per-block per-k anchor partials
__device__ int    g_count = 0;               // completion ticket (self-reset)

// ---------------- tiled transpose: [N][256] -> [256][NMAX] ----------------
__global__ void transpose_kernel(const float* __restrict__ s,
                                 const float* __restrict__ t,
                                 int Ns, int Nt) {
    __shared__ float tile[32][33];
    const float* src; float* dst; int N;
    if (blockIdx.z == 0) { src = s; dst = g_sT; N = Ns; }
    else                 { src = t; dst = g_tT; N = Nt; }
    const int tx = threadIdx.x, ty = threadIdx.y;  // 32 x 8
    const int r0 = blockIdx.x * 32, c0 = blockIdx.y * 32;
    #pragma unroll
    for (int i = 0; i < 4; i++) {
        int r = r0 + ty + i * 8;
        if (r < N) tile[ty + i * 8][tx] = src[r * KD + c0 + tx];
    }
    __syncthreads();
    #pragma unroll
    for (int i = 0; i < 4; i++) {
        int c  = c0 + ty + i * 8;
        int rr = r0 + tx;
        if (rr < N) dst[c * NMAX + rr] = tile[tx][ty + i * 8];
    }
}

// monotone value -> bucket map: linear over [-4,4], clamped
__device__ __forceinline__ int bucket_of(float v) {
    int bi = __float2int_rd(v * 64.0f + 256.0f);   // 64 buckets per unit
    return min(max(bi, 0), NB - 1);
}

// ---------------- fused: bucket counting-sort pair-sums + ALM + finalize ----
__global__ void __launch_bounds__(THREADS) fused_kernel(
    const float* __restrict__ s, const float* __restrict__ t,
    const void* __restrict__ rows_raw, const void* __restrict__ cols_raw,
    float* __restrict__ out, int Ns, int Nt, int nb)
{
    __shared__ float  ysc[NMAX];      // y scattered in bucket order (Nt entries)
    __shared__ int    bcnt[NB + 1];   // histogram -> exclusive prefix counts
    __shared__ float  bsum[NB + 1];   // per-bucket sums -> exclusive prefix
    __shared__ int    boff[NB];       // scatter cursors
    __shared__ int    iwarp[16];
    __shared__ float  fwarp[16];
    __shared__ double dwarp[16];
    __shared__ int    slast;

    const int tid  = threadIdx.x;
    const int lane = tid & 31;
    const int wid  = tid >> 5;
    const int b    = blockIdx.x;

    if (b >= KD) {
        // ======== ALM blocks: anchor-pair L1 sums ========
        // coord = tid & 255 owns plane coordinate; tid>>8 splits the anchor slice.
        __shared__ int is64;
        if (tid == 0) {
            const int* r32 = (const int*)rows_raw;
            is64 = (r32[1] == 0 && r32[3] == 0 && r32[5] == 0) ? 1 : 0;
        }
        __syncthreads();
        const int a = b - KD;
        const int coord = tid & 255;
        const int half  = tid >> 8;
        const int chunk = (nb + ALM_BLOCKS - 1) / ALM_BLOCKS;
        const int lo = a * chunk, hi = min(nb, lo + chunk);
        const long long* r64 = (const long long*)rows_raw;
        const long long* c64 = (const long long*)cols_raw;
        const int* r32 = (const int*)rows_raw;
        const int* c32 = (const int*)cols_raw;
        double acc = 0.0;
        for (int bi = lo + half; bi < hi; bi += 2) {
            long long r = is64 ? r64[bi] : (long long)r32[bi];
            long long c = is64 ? c64[bi] : (long long)c32[bi];
            acc += (double)fabsf(s[r * KD + coord] - t[c * KD + coord]);
        }
        #pragma unroll
        for (int o = 16; o > 0; o >>= 1) acc += __shfl_down_sync(0xffffffffu, acc, o);
        if (lane == 0) dwarp[wid] = acc;
        __syncthreads();
        if (tid == 0) {
            #pragma unroll
            for (int k = 0; k < NRK; k++)
                g_almp[a * NRK + k] = dwarp[2 * k] + dwarp[2 * k + 1]
                                    + dwarp[8 + 2 * k] + dwarp[9 + 2 * k];
        }
    } else {
        // ======== column blocks: exact all-pairs L1 via bucket counting ======
        const float* ycol = g_tT + (size_t)b * NMAX;
        const float* xcol = g_sT + (size_t)b * NMAX;

        // zero histogram (one bucket per thread)
        bcnt[tid] = 0; bsum[tid] = 0.f;
        if (tid == 0) { bcnt[NB] = 0; bsum[NB] = 0.f; }

        // prefetch x early (latency overlaps histogram phase)
        float x[XS];
        bool  xact[XS];
        #pragma unroll
        for (int u = 0; u < XS; u++) {
            int i = tid + u * THREADS;
            xact[u] = (i < Ns);
            x[u]    = xcol[min(i, NMAX - 1)];
        }
        __syncthreads();

        // load y, histogram counts + sums
        float yv[YS];
        int   ybi[YS];
        bool  yact[YS];
        #pragma unroll
        for (int u = 0; u < YS; u++) {
            int j = tid + u * THREADS;
            yact[u] = (j < Nt);
            if (yact[u]) {
                float v = ycol[j];
                int bi = bucket_of(v);
                yv[u] = v; ybi[u] = bi;
                atomicAdd(&bcnt[bi], 1);
                atomicAdd(&bsum[bi], v);
            }
        }
        __syncthreads();

        // exclusive scan of NB buckets (one per thread) + cross-warp offsets
        {
            const int   c0 = bcnt[tid];
            const float s0 = bsum[tid];
            int   ci = c0;
            float si = s0;
            #pragma unroll
            for (int o = 1; o < 32; o <<= 1) {
                int   nc  = __shfl_up_sync(0xffffffffu, ci, o);
                float nsv = __shfl_up_sync(0xffffffffu, si, o);
                if (lane >= o) { ci += nc; si += nsv; }
            }
            if (lane == 31) { iwarp[wid] = ci; fwarp[wid] = si; }
            __syncthreads();
            int   coff = 0;
            float soff = 0.f;
            #pragma unroll
            for (int w = 0; w < 16; w++)
                if (w < wid) { coff += iwarp[w]; soff += fwarp[w]; }
            const int   ce = coff + ci - c0;   // exclusive prefix
            const float se = soff + si - s0;
            // each thread writes only its own slot: no cross-thread hazard
            bcnt[tid] = ce;
            boff[tid] = ce;
            bsum[tid] = se;
            if (tid == THREADS - 1) {
                bcnt[NB] = ce + c0;   // = Nt
                bsum[NB] = se + s0;   // = Ptot
            }
        }
        __syncthreads();

        // scatter y into bucket order
        #pragma unroll
        for (int u = 0; u < YS; u++) {
            if (yact[u]) {
                int p = atomicAdd(&boff[ybi[u]], 1);
                ysc[p] = yv[u];
            }
        }
        __syncthreads();

        const float Ptot = bsum[NB];

        // per-x: prefix from bucket table + exact partial-bucket scan
        double acc = 0.0;
        #pragma unroll
        for (int u = 0; u < XS; u++) {
            if (!xact[u]) continue;
            const float xv = x[u];
            const int bx  = bucket_of(xv);
            const int beg = bcnt[bx];
            const int end = bcnt[bx + 1];
            int   c = beg;
            float P = bsum[bx];
            for (int idx = beg; idx < end; idx++) {
                float yy = ysc[idx];
                if (yy <= xv) { c++; P += yy; }
            }
            acc += (double)(xv * (float)(2 * c - Nt) + Ptot - 2.f * P);
        }

        #pragma unroll
        for (int o = 16; o > 0; o >>= 1) acc += __shfl_down_sync(0xffffffffu, acc, o);
        if (lane == 0) dwarp[wid] = acc;
        __syncthreads();
        if (tid == 0) {
            double sum = 0.0;
            #pragma unroll
            for (int w = 0; w < 16; w++) sum += dwarp[w];
            g_colp[b] = sum;
        }
    }

    // ======== completion ticket: last block finalizes ========
    if (tid == 0) {
        __threadfence();
        int tk = atomicAdd(&g_count, 1);
        slast = (tk == TOTAL_BLOCKS - 1) ? 1 : 0;
    }
    __syncthreads();
    if (!slast) return;
    __threadfence();

    // reduce g_colp (256 doubles) by k-groups of 64 (threads 0..255)
    double vv = (tid < KD) ? g_colp[tid] : 0.0;
    #pragma unroll
    for (int o = 16; o > 0; o >>= 1) vv += __shfl_down_sync(0xffffffffu, vv, o);
    if (lane == 0) dwarp[wid] = vv;
    __syncthreads();
    if (tid == 0) {
        const double params[NRK] = {0.4, 0.2, 0.2, 0.2};
        const double EPS = 3.0;
        const double nb_notB = (double)Ns * (double)Nt - (double)nb;
        double ret = 0.0;
        #pragma unroll
        for (int k = 0; k < NRK; k++) {
            double all = dwarp[2 * k] + dwarp[2 * k + 1];
            double alm = 0.0;
            #pragma unroll
            for (int a = 0; a < ALM_BLOCKS; a++) alm += g_almp[a * NRK + k];
            double notalm = all - alm;
            double lk = alm * nb_notB + (EPS * nb_notB - notalm) * (double)nb;
            ret += params[k] * lk / (double)DW;
        }
        out[0] = (float)(ret / ((double)Ns * (double)Nt));
        g_count = 0;  // reset for next graph replay
    }
}

extern "C" void kernel_launch(void* const* d_in, const int* in_sizes, int n_in,
                              void* d_out, int out_size) {
    const float* s = (const float*)d_in[0];
    const float* t = (const float*)d_in[1];
    const void* rows = d_in[2];
    const void* cols = d_in[3];
    int Ns = in_sizes[0] / KD;
    int Nt = in_sizes[1] / KD;
    int nb = in_sizes[2];
    int nmax = Ns > Nt ? Ns : Nt;

    dim3 tgrid((nmax + 31) / 32, KD / 32, 2);
    dim3 tblk(32, 8, 1);
    transpose_kernel<<<tgrid, tblk>>>(s, t, Ns, Nt);
    fused_kernel<<<TOTAL_BLOCKS, THREADS>>>(s, t, rows, cols,
                                            (float*)d_out, Ns, Nt, nb);
}

// round 11
// speedup vs baseline: 1.5317x; 1.5317x over previous
#include <cuda_runtime.h>

#define NRK 4
#define DW  64
#define KD  256            // NR*D plane stride
#define THREADS 256
#define NB  512            // value buckets (width 1/64 over [-4,4])
#define YS  8              // y slots per thread (Nt <= 2048)
#define XS  8              // x slots per thread (Ns <= 2048)
#define PER 8              // elements per thread in the element scan
#define PAD 2048
#define ALM_BLOCKS 8
#define NMAX 2048          // padded column stride
#define TOTAL_BLOCKS (KD + ALM_BLOCKS)

// Static scratch (no allocation). Zero-init at load; pads never written -> 0.
__device__ float  g_sT[KD * NMAX];           // s transposed+padded: [KD][NMAX]
__device__ float  g_tT[KD * NMAX];           // t transposed+padded: [KD][NMAX]
__device__ double g_colp[KD];                // per-column partials
__device__ double g_almp[ALM_BLOCKS * NRK];  // per-block per-k anchor partials
__device__ int    g_count = 0;               // completion ticket (self-reset)

// ---------------- tiled transpose: [N][256] -> [256][NMAX] ----------------
__global__ void transpose_kernel(const float* __restrict__ s,
                                 const float* __restrict__ t,
                                 int Ns, int Nt) {
    __shared__ float tile[32][33];
    const float* src; float* dst; int N;
    if (blockIdx.z == 0) { src = s; dst = g_sT; N = Ns; }
    else                 { src = t; dst = g_tT; N = Nt; }
    const int tx = threadIdx.x, ty = threadIdx.y;  // 32 x 8
    const int r0 = blockIdx.x * 32, c0 = blockIdx.y * 32;
    #pragma unroll
    for (int i = 0; i < 4; i++) {
        int r = r0 + ty + i * 8;
        if (r < N) tile[ty + i * 8][tx] = src[r * KD + c0 + tx];
    }
    __syncthreads();
    #pragma unroll
    for (int i = 0; i < 4; i++) {
        int c  = c0 + ty + i * 8;
        int rr = r0 + tx;
        if (rr < N) dst[c * NMAX + rr] = tile[tx][ty + i * 8];
    }
}

// monotone value -> bucket map: linear over [-4,4], clamped
__device__ __forceinline__ int bucket_of(float v) {
    int bi = __float2int_rd(v * 64.0f + 256.0f);   // 64 buckets per unit
    return min(max(bi, 0), NB - 1);
}

// ---------------- fused: bucket counting-sort pair-sums + ALM + finalize ----
__global__ void __launch_bounds__(THREADS) fused_kernel(
    const float* __restrict__ s, const float* __restrict__ t,
    const void* __restrict__ rows_raw, const void* __restrict__ cols_raw,
    float* __restrict__ out, int Ns, int Nt, int nb)
{
    __shared__ float  ysc[PAD];       // y scattered in bucket order (Nt entries)
    __shared__ float  ypre[PAD + 1];  // element-level prefix: ypre[i] = sum first i
    __shared__ int    bcnt[NB + 1];   // histogram -> exclusive prefix counts
    __shared__ int    boff[NB];       // scatter cursors
    __shared__ int    iwarp[8];
    __shared__ float  fwarp[8];
    __shared__ double dwarp[8];
    __shared__ int    slast;

    const int tid  = threadIdx.x;
    const int lane = tid & 31;
    const int wid  = tid >> 5;
    const int b    = blockIdx.x;

    if (b >= KD) {
        // ======== ALM blocks: anchor-pair L1 sums, sliced over anchors ========
        __shared__ int is64;
        if (tid == 0) {
            const int* r32 = (const int*)rows_raw;
            is64 = (r32[1] == 0 && r32[3] == 0 && r32[5] == 0) ? 1 : 0;
        }
        __syncthreads();
        const int a = b - KD;
        const int chunk = (nb + ALM_BLOCKS - 1) / ALM_BLOCKS;
        const int lo = a * chunk, hi = min(nb, lo + chunk);
        const long long* r64 = (const long long*)rows_raw;
        const long long* c64 = (const long long*)cols_raw;
        const int* r32 = (const int*)rows_raw;
        const int* c32 = (const int*)cols_raw;
        double acc = 0.0;
        for (int bi = lo; bi < hi; bi++) {
            long long r = is64 ? r64[bi] : (long long)r32[bi];
            long long c = is64 ? c64[bi] : (long long)c32[bi];
            acc += (double)fabsf(s[r * KD + tid] - t[c * KD + tid]);
        }
        #pragma unroll
        for (int o = 16; o > 0; o >>= 1) acc += __shfl_down_sync(0xffffffffu, acc, o);
        if (lane == 0) dwarp[wid] = acc;
        __syncthreads();
        if (tid == 0) {
            #pragma unroll
            for (int k = 0; k < NRK; k++)
                g_almp[a * NRK + k] = dwarp[2 * k] + dwarp[2 * k + 1];
        }
    } else {
        // ======== column blocks: exact all-pairs L1 via bucket counting ======
        const float* ycol = g_tT + (size_t)b * NMAX;
        const float* xcol = g_sT + (size_t)b * NMAX;

        // zero histogram (2 buckets per thread)
        bcnt[2 * tid] = 0;
        bcnt[2 * tid + 1] = 0;
        if (tid == 0) bcnt[NB] = 0;

        // prefetch x early (latency overlaps histogram phase)
        float x[XS];
        bool  xact[XS];
        #pragma unroll
        for (int u = 0; u < XS; u++) {
            int i = tid + u * THREADS;
            xact[u] = (i < Ns);
            x[u]    = xcol[min(i, NMAX - 1)];
        }
        __syncthreads();

        // load y, histogram counts only (no float atomics)
        float yv[YS];
        int   ybi[YS];
        bool  yact[YS];
        #pragma unroll
        for (int u = 0; u < YS; u++) {
            int j = tid + u * THREADS;
            yact[u] = (j < Nt);
            if (yact[u]) {
                float v = ycol[j];
                int bi = bucket_of(v);
                yv[u] = v; ybi[u] = bi;
                atomicAdd(&bcnt[bi], 1);
            }
        }
        __syncthreads();

        // exclusive scan of NB int counts: 2 per thread + shfl
        {
            const int c0 = bcnt[2 * tid], c1 = bcnt[2 * tid + 1];
            const int tc = c0 + c1;
            int ci = tc;
            #pragma unroll
            for (int o = 1; o < 32; o <<= 1) {
                int nc = __shfl_up_sync(0xffffffffu, ci, o);
                if (lane >= o) ci += nc;
            }
            if (lane == 31) iwarp[wid] = ci;
            __syncthreads();   // also: all bcnt reads done before overwrite
            int coff = 0;
            #pragma unroll
            for (int w = 0; w < 8; w++)
                if (w < wid) coff += iwarp[w];
            const int cbase = coff + ci - tc;
            bcnt[2 * tid]     = cbase;
            bcnt[2 * tid + 1] = cbase + c0;
            boff[2 * tid]     = cbase;
            boff[2 * tid + 1] = cbase + c0;
            if (tid == THREADS - 1) bcnt[NB] = cbase + tc;   // = Nt
        }
        __syncthreads();

        // scatter y into bucket order
        #pragma unroll
        for (int u = 0; u < YS; u++) {
            if (yact[u]) {
                int p = atomicAdd(&boff[ybi[u]], 1);
                ysc[p] = yv[u];
            }
        }
        __syncthreads();

        // element-level exclusive prefix over scattered y (pads -> 0)
        {
            const int base = tid * PER;
            float pre[PER];
            float run = 0.f;
            #pragma unroll
            for (int m = 0; m < PER; m++) {
                int idx = base + m;
                float vv = (idx < Nt) ? ysc[idx] : 0.f;
                run += vv;
                pre[m] = run;
            }
            float incl = run;
            #pragma unroll
            for (int o = 1; o < 32; o <<= 1) {
                float n = __shfl_up_sync(0xffffffffu, incl, o);
                if (lane >= o) incl += n;
            }
            if (lane == 31) fwarp[wid] = incl;
            const float excl = incl - run;
            __syncthreads();
            float woff = 0.f;
            #pragma unroll
            for (int w = 0; w < 8; w++)
                if (w < wid) woff += fwarp[w];
            const float off = woff + excl;
            #pragma unroll
            for (int m = 0; m < PER; m++) ypre[base + m + 1] = pre[m] + off;
            if (tid == 0) ypre[0] = 0.f;
        }
        __syncthreads();

        const float Ptot = ypre[Nt];

        // per-x: bucket-boundary prefix + exact partial-bucket scan
        double acc = 0.0;
        #pragma unroll
        for (int u = 0; u < XS; u++) {
            if (!xact[u]) continue;
            const float xv = x[u];
            const int bx  = bucket_of(xv);
            const int beg = bcnt[bx];
            const int end = bcnt[bx + 1];
            int   c = beg;
            float P = ypre[beg];   // sum of all y in buckets below bx
            for (int idx = beg; idx < end; idx++) {
                float yy = ysc[idx];
                if (yy <= xv) { c++; P += yy; }
            }
            acc += (double)(xv * (float)(2 * c - Nt) + Ptot - 2.f * P);
        }

        #pragma unroll
        for (int o = 16; o > 0; o >>= 1) acc += __shfl_down_sync(0xffffffffu, acc, o);
        if (lane == 0) dwarp[wid] = acc;
        __syncthreads();
        if (tid == 0) {
            double sum = 0.0;
            #pragma unroll
            for (int w = 0; w < 8; w++) sum += dwarp[w];
            g_colp[b] = sum;
        }
    }

    // ======== completion ticket: last block finalizes ========
    if (tid == 0) {
        __threadfence();
        int tk = atomicAdd(&g_count, 1);
        slast = (tk == TOTAL_BLOCKS - 1) ? 1 : 0;
    }
    __syncthreads();
    if (!slast) return;
    __threadfence();

    // reduce g_colp (256 doubles) by k-groups of 64
    double vv = g_colp[tid];
    #pragma unroll
    for (int o = 16; o > 0; o >>= 1) vv += __shfl_down_sync(0xffffffffu, vv, o);
    if (lane == 0) dwarp[wid] = vv;
    __syncthreads();
    if (tid == 0) {
        const double params[NRK] = {0.4, 0.2, 0.2, 0.2};
        const double EPS = 3.0;
        const double nb_notB = (double)Ns * (double)Nt - (double)nb;
        double ret = 0.0;
        #pragma unroll
        for (int k = 0; k < NRK; k++) {
            double all = dwarp[2 * k] + dwarp[2 * k + 1];
            double alm = 0.0;
            #pragma unroll
            for (int a = 0; a < ALM_BLOCKS; a++) alm += g_almp[a * NRK + k];
            double notalm = all - alm;
            double lk = alm * nb_notB + (EPS * nb_notB - notalm) * (double)nb;
            ret += params[k] * lk / (double)DW;
        }
        out[0] = (float)(ret / ((double)Ns * (double)Nt));
        g_count = 0;  // reset for next graph replay
    }
}

extern "C" void kernel_launch(void* const* d_in, const int* in_sizes, int n_in,
                              void* d_out, int out_size) {
    const float* s = (const float*)d_in[0];
    const float* t = (const float*)d_in[1];
    const void* rows = d_in[2];
    const void* cols = d_in[3];
    int Ns = in_sizes[0] / KD;
    int Nt = in_sizes[1] / KD;
    int nb = in_sizes[2];
    int nmax = Ns > Nt ? Ns : Nt;

    dim3 tgrid((nmax + 31) / 32, KD / 32, 2);
    dim3 tblk(32, 8, 1);
    transpose_kernel<<<tgrid, tblk>>>(s, t, Ns, Nt);
    fused_kernel<<<TOTAL_BLOCKS, THREADS>>>(s, t, rows, cols,
                                            (float*)d_out, Ns, Nt, nb);
}